// round 6
// baseline (speedup 1.0000x reference)
#include <cuda_runtime.h>
#include <cstdint>
#include <math_constants.h>

// Problem constants: B=2, N=131072, M=512, G=20
#define BB 2
#define NN 131072
#define MM 512
#define GG 20
#define VV 8000
#define VOXINV 2.0f

#define NBLK 148                // one wave on 148+ SMs
#define BPB  74                 // blocks per batch
#define NTHR 512                // 16 warps per CTA
#define GROUPS 32768            // NN/4 float4-groups per batch
#define MASKW 250               // VV bits / 32
#define ACCW  40000             // BB*VV*10 floats / 4 = uint4 words

// Device scratch. g_minc seeded +inf by static init, re-armed by the k2
// epilogue every launch (graph nodes serialize -> deterministic).
__device__ unsigned int g_minc[BB * 3] = {
    0x7F800000u, 0x7F800000u, 0x7F800000u,
    0x7F800000u, 0x7F800000u, 0x7F800000u};
__device__ float4       g_spts[BB * MM];      // compacted sampled points
__device__ float        g_acc[BB * VV * 10];  // cnt, sx..sz, xx,xy,xz,yy,yz,zz
__device__ unsigned int g_done;               // k2 completion counter

__device__ __forceinline__ int voxel_of(float px, float py, float pz,
                                        float n0, float n1, float n2) {
    int vx = (int)floorf((px - n0) * VOXINV);
    int vy = (int)floorf((py - n1) * VOXINV);
    int vz = (int)floorf((pz - n2) * VOXINV);
    vx = min(max(vx, 0), GG - 1);
    vy = min(max(vy, 0), GG - 1);
    vz = min(max(vz, 0), GG - 1);
    return (vx * GG + vy) * GG + vz;
}

// ============================================================================
// K1: zero g_acc + g_done, compact sampled points, global per-batch min.
// ============================================================================
__global__ void __launch_bounds__(NTHR)
k1_min(const float* __restrict__ x, const int* __restrict__ sidx) {
    const int bid = blockIdx.x, tid = threadIdx.x;
    const int b = (bid < BPB) ? 0 : 1, br = bid - b * BPB;
    const int lane = tid & 31, w = tid >> 5;
    const int t = bid * NTHR + tid;      // 0..75775
    __shared__ float s_red[16 * 3];

    // zero accumulators (40000 uint4 over 75776 threads: single shot)
    if (t < ACCW) ((uint4*)g_acc)[t] = make_uint4(0u, 0u, 0u, 0u);
    if (t == 0) g_done = 0u;

    // compact sampled points (one scattered gather, once)
    if (t < BB * MM) {
        int sb = t >> 9;
        int i = __ldg(sidx + t);
        const float* p = x + ((size_t)sb * NN + i) * 3;
        g_spts[t] = make_float4(__ldg(p), __ldg(p + 1), __ldg(p + 2), 0.0f);
    }

    // coordinate min: exactly one float4-group (4 points) per active thread
    float m0 = CUDART_INF_F, m1 = CUDART_INF_F, m2 = CUDART_INF_F;
    {
        const float4* xb = (const float4*)(x + (size_t)b * NN * 3);
        int g = br * NTHR + tid;
        if (g < GROUPS) {
            float4 f0 = __ldg(xb + (size_t)g * 3 + 0);
            float4 f1 = __ldg(xb + (size_t)g * 3 + 1);
            float4 f2 = __ldg(xb + (size_t)g * 3 + 2);
            m0 = fminf(fminf(f0.x, f0.w), fminf(f1.z, f2.y));
            m1 = fminf(fminf(f0.y, f1.x), fminf(f1.w, f2.z));
            m2 = fminf(fminf(f0.z, f1.y), fminf(f2.x, f2.w));
        }
    }
#pragma unroll
    for (int o = 16; o > 0; o >>= 1) {
        m0 = fminf(m0, __shfl_xor_sync(0xFFFFFFFFu, m0, o));
        m1 = fminf(m1, __shfl_xor_sync(0xFFFFFFFFu, m1, o));
        m2 = fminf(m2, __shfl_xor_sync(0xFFFFFFFFu, m2, o));
    }
    if (lane == 0) { s_red[w*3+0] = m0; s_red[w*3+1] = m1; s_red[w*3+2] = m2; }
    __syncthreads();
    if (tid == 0) {
        float r0 = s_red[0], r1 = s_red[1], r2 = s_red[2];
#pragma unroll
        for (int k = 1; k < 16; k++) {
            r0 = fminf(r0, s_red[k*3+0]);
            r1 = fminf(r1, s_red[k*3+1]);
            r2 = fminf(r2, s_red[k*3+2]);
        }
        // positive floats: uint bit order == float order
        atomicMin(&g_minc[b*3+0], __float_as_uint(r0));
        atomicMin(&g_minc[b*3+1], __float_as_uint(r1));
        atomicMin(&g_minc[b*3+2], __float_as_uint(r2));
    }
}

// ============================================================================
// K2: smem mark + masked accumulation + last-block output epilogue.
// ============================================================================
__global__ void __launch_bounds__(NTHR)
k2_accum(const float* __restrict__ x, float* __restrict__ out) {
    const int bid = blockIdx.x, tid = threadIdx.x;
    const int b = (bid < BPB) ? 0 : 1, br = bid - b * BPB;
    __shared__ unsigned int s_mask[MASKW];
    __shared__ unsigned int s_last;

    if (tid < MASKW) s_mask[tid] = 0u;
    const float n0 = __uint_as_float(g_minc[b*3+0]);
    const float n1 = __uint_as_float(g_minc[b*3+1]);
    const float n2 = __uint_as_float(g_minc[b*3+2]);
    __syncthreads();

    // mark this batch's 512 sampled voxels (dense buffer, 1 point/thread)
    {
        float4 p = g_spts[b * MM + tid - (tid >= MM ? MM : 0)];
        // only first MM threads mark (avoid double-marking; harmless anyway,
        // but keep it exact): recompute guarded
    }
    if (tid < MM) {
        float4 p = g_spts[b * MM + tid];
        int v = voxel_of(p.x, p.y, p.z, n0, n1, n2);
        atomicOr(&s_mask[v >> 5], 1u << (v & 31));
    }
    __syncthreads();

    // masked accumulation: exactly one float4-group (4 points) per thread
    {
        const float4* xb = (const float4*)(x + (size_t)b * NN * 3);
        int g = br * NTHR + tid;
        if (g < GROUPS) {
            float4 f0 = __ldg(xb + (size_t)g * 3 + 0);
            float4 f1 = __ldg(xb + (size_t)g * 3 + 1);
            float4 f2 = __ldg(xb + (size_t)g * 3 + 2);
            float px[4] = {f0.x, f0.w, f1.z, f2.y};
            float py[4] = {f0.y, f1.x, f1.w, f2.z};
            float pz[4] = {f0.z, f1.y, f2.x, f2.w};
#pragma unroll
            for (int k = 0; k < 4; k++) {
                int v = voxel_of(px[k], py[k], pz[k], n0, n1, n2);
                if (s_mask[v >> 5] & (1u << (v & 31))) {
                    float* a = &g_acc[(size_t)(b * VV + v) * 10];
                    atomicAdd(a + 0, 1.0f);
                    atomicAdd(a + 1, px[k]);
                    atomicAdd(a + 2, py[k]);
                    atomicAdd(a + 3, pz[k]);
                    atomicAdd(a + 4, px[k] * px[k]);
                    atomicAdd(a + 5, px[k] * py[k]);
                    atomicAdd(a + 6, px[k] * pz[k]);
                    atomicAdd(a + 7, py[k] * py[k]);
                    atomicAdd(a + 8, py[k] * pz[k]);
                    atomicAdd(a + 9, pz[k] * pz[k]);
                }
            }
        }
    }

    // ---- completion handshake: last-arriving block runs the epilogue ----
    __syncthreads();
    if (tid == 0) {
        __threadfence();             // order atomics before the counter
        s_last = (atomicAdd(&g_done, 1u) == NBLK - 1) ? 1u : 0u;
    }
    __syncthreads();
    if (!s_last) return;

    // ===== epilogue (one block, 512 threads x 2 outputs) =====
    float nall[6];
#pragma unroll
    for (int k = 0; k < 6; k++) nall[k] = __uint_as_float(g_minc[k]);

#pragma unroll
    for (int r = 0; r < 2; r++) {
        int t = r * NTHR + tid;          // 0..1023 = eb*MM + j
        int eb = t >> 9;
        float4 p = g_spts[t];
        int v = voxel_of(p.x, p.y, p.z, nall[eb*3+0], nall[eb*3+1], nall[eb*3+2]);
        const float* a = &g_acc[(size_t)(eb * VV + v) * 10];

        float c0 = __ldcg(a + 0);
        float s1 = __ldcg(a + 1), s2 = __ldcg(a + 2), s3 = __ldcg(a + 3);
        float q4 = __ldcg(a + 4), q5 = __ldcg(a + 5), q6 = __ldcg(a + 6);
        float q7 = __ldcg(a + 7), q8 = __ldcg(a + 8), q9 = __ldcg(a + 9);

        float inv = 1.0f / fmaxf(c0, 1.0f);
        float mx = s1 * inv, my = s2 * inv, mz = s3 * inv;
        float cxx = q4 * inv - mx * mx;
        float cxy = q5 * inv - mx * my;
        float cxz = q6 * inv - mx * mz;
        float cyy = q7 * inv - my * my;
        float cyz = q8 * inv - my * mz;
        float czz = q9 * inv - mz * mz;

        float* o = out + (size_t)t * 12;
        o[0] = mx;  o[1] = my;  o[2] = mz;
        o[3] = cxx; o[4] = cxy; o[5] = cxz;
        o[6] = cxy; o[7] = cyy; o[8] = cyz;
        o[9] = cxz; o[10] = cyz; o[11] = czz;
    }

    // re-arm min for the next replay (all k2 blocks already read g_minc)
    if (tid < BB * 3) g_minc[tid] = 0x7F800000u;
}

// ---------------------------------------------------------------------------
extern "C" void kernel_launch(void* const* d_in, const int* in_sizes, int n_in,
                              void* d_out, int out_size) {
    const float* x    = (const float*)d_in[0];   // (B, N, 3) f32
    const int*   sidx = (const int*)d_in[1];     // (B, M) i32
    float*       out  = (float*)d_out;           // (B, M, 12) f32

    k1_min<<<NBLK, NTHR>>>(x, sidx);
    k2_accum<<<NBLK, NTHR>>>(x, out);
}

// round 7
// speedup vs baseline: 1.2339x; 1.2339x over previous
#include <cuda_runtime.h>
#include <cstdint>
#include <math_constants.h>

// Problem constants: B=2, N=131072, M=512, G=20
#define BB 2
#define NN 131072
#define MM 512
#define GG 20
#define VV 8000
#define VOXINV 2.0f

#define NBLK 148                // one wave on 148+ SMs
#define BPB  74                 // blocks per batch
#define NTHR 512
#define GROUPS 32768            // NN/4 float4-groups per batch
#define MASKW 250               // VV bits / 32

// Device scratch. g_minc seeded +inf and g_acc zeroed at module load;
// k3 restores both every launch (graph nodes serialize -> deterministic).
__device__ unsigned int g_minc[BB * 3] = {
    0x7F800000u, 0x7F800000u, 0x7F800000u,
    0x7F800000u, 0x7F800000u, 0x7F800000u};
__device__ float4 g_spts[BB * MM];      // compacted sampled points (.w unused)
__device__ float  g_acc[BB * VV * 10];  // zero-init; kept zero by k3 cleanup

__device__ __forceinline__ int voxel_of(float px, float py, float pz,
                                        float n0, float n1, float n2) {
    int vx = (int)floorf((px - n0) * VOXINV);
    int vy = (int)floorf((py - n1) * VOXINV);
    int vz = (int)floorf((pz - n2) * VOXINV);
    vx = min(max(vx, 0), GG - 1);
    vy = min(max(vy, 0), GG - 1);
    vz = min(max(vz, 0), GG - 1);
    return (vx * GG + vy) * GG + vz;
}

// ============================================================================
// K1: compact sampled points + global per-batch min (atomicMin on uint bits).
// ============================================================================
__global__ void __launch_bounds__(NTHR)
k1_min(const float* __restrict__ x, const int* __restrict__ sidx) {
    // Let k2 launch ASAP: its prologue (x loads, smem zero) is k1-independent.
    cudaTriggerProgrammaticLaunchCompletion();

    const int bid = blockIdx.x, tid = threadIdx.x;
    const int b = (bid < BPB) ? 0 : 1, br = bid - b * BPB;
    const int lane = tid & 31, w = tid >> 5;
    const int t = bid * NTHR + tid;
    __shared__ float s_red[16 * 3];

    // compact sampled points (one scattered gather per launch)
    if (t < BB * MM) {
        int sb = t >> 9;
        int i = __ldg(sidx + t);
        const float* p = x + ((size_t)sb * NN + i) * 3;
        g_spts[t] = make_float4(__ldg(p), __ldg(p + 1), __ldg(p + 2), 0.0f);
    }

    // coordinate min: one float4-group (4 points) per active thread
    float m0 = CUDART_INF_F, m1 = CUDART_INF_F, m2 = CUDART_INF_F;
    {
        const float4* xb = (const float4*)(x + (size_t)b * NN * 3);
        int g = br * NTHR + tid;
        if (g < GROUPS) {
            float4 f0 = __ldg(xb + (size_t)g * 3 + 0);
            float4 f1 = __ldg(xb + (size_t)g * 3 + 1);
            float4 f2 = __ldg(xb + (size_t)g * 3 + 2);
            m0 = fminf(fminf(f0.x, f0.w), fminf(f1.z, f2.y));
            m1 = fminf(fminf(f0.y, f1.x), fminf(f1.w, f2.z));
            m2 = fminf(fminf(f0.z, f1.y), fminf(f2.x, f2.w));
        }
    }
#pragma unroll
    for (int o = 16; o > 0; o >>= 1) {
        m0 = fminf(m0, __shfl_xor_sync(0xFFFFFFFFu, m0, o));
        m1 = fminf(m1, __shfl_xor_sync(0xFFFFFFFFu, m1, o));
        m2 = fminf(m2, __shfl_xor_sync(0xFFFFFFFFu, m2, o));
    }
    if (lane == 0) { s_red[w*3+0] = m0; s_red[w*3+1] = m1; s_red[w*3+2] = m2; }
    __syncthreads();
    if (tid == 0) {
        float r0 = s_red[0], r1 = s_red[1], r2 = s_red[2];
#pragma unroll
        for (int k = 1; k < 16; k++) {
            r0 = fminf(r0, s_red[k*3+0]);
            r1 = fminf(r1, s_red[k*3+1]);
            r2 = fminf(r2, s_red[k*3+2]);
        }
        // positive floats: uint bit order == float order
        atomicMin(&g_minc[b*3+0], __float_as_uint(r0));
        atomicMin(&g_minc[b*3+1], __float_as_uint(r1));
        atomicMin(&g_minc[b*3+2], __float_as_uint(r2));
    }
}

// ============================================================================
// K2 (PDL secondary): prologue loads x + zeroes mask, then grid-dep sync,
// then mark + masked accumulation.
// ============================================================================
__global__ void __launch_bounds__(NTHR)
k2_accum(const float* __restrict__ x) {
    cudaTriggerProgrammaticLaunchCompletion();   // let k3 stage early too

    const int bid = blockIdx.x, tid = threadIdx.x;
    const int b = (bid < BPB) ? 0 : 1, br = bid - b * BPB;
    __shared__ unsigned int s_mask[MASKW];

    if (tid < MASKW) s_mask[tid] = 0u;

    // ---- prologue: this thread's 4 points (independent of k1) ----
    const int g = br * NTHR + tid;
    float4 f0, f1, f2;
    const bool active = (g < GROUPS);
    if (active) {
        const float4* xb = (const float4*)(x + (size_t)b * NN * 3);
        f0 = __ldg(xb + (size_t)g * 3 + 0);
        f1 = __ldg(xb + (size_t)g * 3 + 1);
        f2 = __ldg(xb + (size_t)g * 3 + 2);
    }

    // ---- wait for k1's g_minc / g_spts ----
    cudaGridDependencySynchronize();

    const float n0 = __uint_as_float(g_minc[b*3+0]);
    const float n1 = __uint_as_float(g_minc[b*3+1]);
    const float n2 = __uint_as_float(g_minc[b*3+2]);

    // mark this batch's 512 sampled voxels (dense buffer, 1 point/thread)
    if (tid < MM) {
        float4 p = g_spts[b * MM + tid];
        int v = voxel_of(p.x, p.y, p.z, n0, n1, n2);
        atomicOr(&s_mask[v >> 5], 1u << (v & 31));
    }
    __syncthreads();

    // masked accumulation
    if (active) {
        float px[4] = {f0.x, f0.w, f1.z, f2.y};
        float py[4] = {f0.y, f1.x, f1.w, f2.z};
        float pz[4] = {f0.z, f1.y, f2.x, f2.w};
#pragma unroll
        for (int k = 0; k < 4; k++) {
            int v = voxel_of(px[k], py[k], pz[k], n0, n1, n2);
            if (s_mask[v >> 5] & (1u << (v & 31))) {
                float* a = &g_acc[(size_t)(b * VV + v) * 10];
                atomicAdd(a + 0, 1.0f);
                atomicAdd(a + 1, px[k]);
                atomicAdd(a + 2, py[k]);
                atomicAdd(a + 3, pz[k]);
                atomicAdd(a + 4, px[k] * px[k]);
                atomicAdd(a + 5, px[k] * py[k]);
                atomicAdd(a + 6, px[k] * pz[k]);
                atomicAdd(a + 7, py[k] * py[k]);
                atomicAdd(a + 8, py[k] * pz[k]);
                atomicAdd(a + 9, pz[k] * pz[k]);
            }
        }
    }
}

// ============================================================================
// K3 (PDL secondary, single block of 1024): gather + finalize output, then
// clean up: zero the touched g_acc entries and re-arm g_minc.
// ============================================================================
__global__ void __launch_bounds__(1024)
k3_out(float* __restrict__ out) {
    cudaGridDependencySynchronize();             // wait for k2's atomics

    const int t = threadIdx.x;                   // 0..1023 = b*MM + j
    const int b = t >> 9;
    const float n0 = __uint_as_float(g_minc[b*3+0]);
    const float n1 = __uint_as_float(g_minc[b*3+1]);
    const float n2 = __uint_as_float(g_minc[b*3+2]);

    float4 p = g_spts[t];
    int v = voxel_of(p.x, p.y, p.z, n0, n1, n2);
    float* a = &g_acc[(size_t)(b * VV + v) * 10];

    float c0 = a[0];
    float s1 = a[1], s2 = a[2], s3 = a[3];
    float q4 = a[4], q5 = a[5], q6 = a[6];
    float q7 = a[7], q8 = a[8], q9 = a[9];

    // all reads done before any thread zeroes shared voxel entries
    __syncthreads();
#pragma unroll
    for (int k = 0; k < 10; k++) a[k] = 0.0f;    // restore zero for next replay
    if (t < BB * 3) g_minc[t] = 0x7F800000u;     // re-arm min

    float inv = 1.0f / fmaxf(c0, 1.0f);
    float mx = s1 * inv, my = s2 * inv, mz = s3 * inv;
    float cxx = q4 * inv - mx * mx;
    float cxy = q5 * inv - mx * my;
    float cxz = q6 * inv - mx * mz;
    float cyy = q7 * inv - my * my;
    float cyz = q8 * inv - my * mz;
    float czz = q9 * inv - mz * mz;

    float* o = out + (size_t)t * 12;
    o[0] = mx;  o[1] = my;  o[2] = mz;
    o[3] = cxx; o[4] = cxy; o[5] = cxz;
    o[6] = cxy; o[7] = cyy; o[8] = cyz;
    o[9] = cxz; o[10] = cyz; o[11] = czz;
}

// ---------------------------------------------------------------------------
extern "C" void kernel_launch(void* const* d_in, const int* in_sizes, int n_in,
                              void* d_out, int out_size) {
    const float* x    = (const float*)d_in[0];   // (B, N, 3) f32
    const int*   sidx = (const int*)d_in[1];     // (B, M) i32
    float*       out  = (float*)d_out;           // (B, M, 12) f32

    k1_min<<<NBLK, NTHR>>>(x, sidx);

    // PDL: k2 and k3 launch early; device-side grid-dep sync orders them.
    cudaLaunchAttribute attrs[1];
    attrs[0].id = cudaLaunchAttributeProgrammaticStreamSerialization;
    attrs[0].val.programmaticStreamSerializationAllowed = 1;

    cudaLaunchConfig_t cfg2 = {};
    cfg2.gridDim = dim3(NBLK);
    cfg2.blockDim = dim3(NTHR);
    cfg2.dynamicSmemBytes = 0;
    cfg2.stream = 0;
    cfg2.attrs = attrs;
    cfg2.numAttrs = 1;
    cudaLaunchKernelEx(&cfg2, k2_accum, x);

    cudaLaunchConfig_t cfg3 = cfg2;
    cfg3.gridDim = dim3(1);
    cfg3.blockDim = dim3(1024);
    cudaLaunchKernelEx(&cfg3, k3_out, out);
}

// round 8
// speedup vs baseline: 1.2449x; 1.0089x over previous
#include <cuda_runtime.h>
#include <cstdint>
#include <math_constants.h>

// Problem constants: B=2, N=131072, M=512, G=20
#define BB 2
#define NN 131072
#define MM 512
#define GG 20
#define VV 8000
#define VOXINV 2.0f

#define NBLK 148                // one wave; all blocks co-resident (<= SM count)
#define BPB  74                 // blocks per batch
#define NTHR 512
#define GROUPS 32768            // NN/4 float4-groups per batch
#define MASKW 250               // VV bits / 32

// Device scratch. g_acc zero at load; K_B keeps it zero (cleans touched
// entries). g_done zero at load; K_B resets it. Graph nodes serialize.
__device__ float        g_pmin[NBLK * 3];     // per-block partial mins
__device__ float4       g_spts[BB * MM];      // compacted sampled points
__device__ float        g_acc[BB * VV * 10];  // cnt, sx..sz, xx,xy,xz,yy,yz,zz
__device__ unsigned int g_done;               // barrier arrival counter

__device__ __forceinline__ int voxel_of(float px, float py, float pz,
                                        float n0, float n1, float n2) {
    int vx = (int)floorf((px - n0) * VOXINV);
    int vy = (int)floorf((py - n1) * VOXINV);
    int vz = (int)floorf((pz - n2) * VOXINV);
    vx = min(max(vx, 0), GG - 1);
    vy = min(max(vy, 0), GG - 1);
    vz = min(max(vz, 0), GG - 1);
    return (vx * GG + vy) * GG + vz;
}

// Re-reduce the 148 partial mins for batch b; 3 warps (w<3), one component
// each, result into s_min[3]. Caller must __syncthreads() after.
__device__ __forceinline__ void rereduce_min(int tid, float* s_min) {
    int w = tid >> 5, lane = tid & 31;
    if (w < 3) {
        float m = CUDART_INF_F;
#pragma unroll
        for (int j = 0; j < NBLK; j += 32) {  // covers both batches? no: see call
            int idx = j + lane;
            if (idx < NBLK) ;  // placeholder (specialized below)
        }
        (void)m;
    }
    (void)s_min;
}

// ============================================================================
// K_A: compact + partial min -> grid barrier (cheap fence) -> mark + accum.
// ============================================================================
__global__ void __launch_bounds__(NTHR)
kA(const float* __restrict__ x, const int* __restrict__ sidx) {
    const int bid = blockIdx.x, tid = threadIdx.x;
    const int b = (bid < BPB) ? 0 : 1, br = bid - b * BPB;
    const int lane = tid & 31, w = tid >> 5;
    const int t = bid * NTHR + tid;
    __shared__ float s_red[16 * 3];
    __shared__ float s_min[3];
    __shared__ unsigned int s_mask[MASKW];

    if (tid < MASKW) s_mask[tid] = 0u;

    // ---- compact sampled points (first 1024 threads = blocks 0 and 1) ----
    if (t < BB * MM) {
        int sb = t >> 9;
        int i = __ldg(sidx + t);
        const float* p = x + ((size_t)sb * NN + i) * 3;
        g_spts[t] = make_float4(__ldg(p), __ldg(p + 1), __ldg(p + 2), 0.0f);
    }

    // ---- this thread's 4 points: used for both min and (later) accum ----
    const int g = br * NTHR + tid;
    const bool active = (g < GROUPS);
    float4 f0, f1, f2;
    float m0 = CUDART_INF_F, m1 = CUDART_INF_F, m2 = CUDART_INF_F;
    if (active) {
        const float4* xb = (const float4*)(x + (size_t)b * NN * 3);
        f0 = __ldg(xb + (size_t)g * 3 + 0);
        f1 = __ldg(xb + (size_t)g * 3 + 1);
        f2 = __ldg(xb + (size_t)g * 3 + 2);
        m0 = fminf(fminf(f0.x, f0.w), fminf(f1.z, f2.y));
        m1 = fminf(fminf(f0.y, f1.x), fminf(f1.w, f2.z));
        m2 = fminf(fminf(f0.z, f1.y), fminf(f2.x, f2.w));
    }
#pragma unroll
    for (int o = 16; o > 0; o >>= 1) {
        m0 = fminf(m0, __shfl_xor_sync(0xFFFFFFFFu, m0, o));
        m1 = fminf(m1, __shfl_xor_sync(0xFFFFFFFFu, m1, o));
        m2 = fminf(m2, __shfl_xor_sync(0xFFFFFFFFu, m2, o));
    }
    if (lane == 0) { s_red[w*3+0] = m0; s_red[w*3+1] = m1; s_red[w*3+2] = m2; }
    __syncthreads();
    if (tid == 0) {
        float r0 = s_red[0], r1 = s_red[1], r2 = s_red[2];
#pragma unroll
        for (int k = 1; k < 16; k++) {
            r0 = fminf(r0, s_red[k*3+0]);
            r1 = fminf(r1, s_red[k*3+1]);
            r2 = fminf(r2, s_red[k*3+2]);
        }
        g_pmin[bid*3+0] = r0; g_pmin[bid*3+1] = r1; g_pmin[bid*3+2] = r2;
    }

    // ---- grid barrier: fence issued while only ~8 stores are in flight ----
    __syncthreads();
    if (tid == 0) {
        __threadfence();                            // publish g_pmin / g_spts
        atomicAdd(&g_done, 1u);
        while (atomicAdd(&g_done, 0u) < NBLK) { __nanosleep(64); }
    }
    __syncthreads();

    // ---- re-reduce this batch's min locally (3 warps, __ldcg = L2 scope) ----
    if (w < 3) {
        float m = CUDART_INF_F;
#pragma unroll
        for (int j = 0; j < NBLK; j += 32) {
            int idx = j + lane;
            if (idx < NBLK)
                m = fminf(m, __ldcg(&g_pmin[idx * 3 + w]));
            // note: reduce over ALL blocks' partials of THIS batch only:
        }
        (void)m;
        // recompute correctly below (batch-restricted)
        m = CUDART_INF_F;
#pragma unroll
        for (int j = 0; j < BPB; j += 32) {
            int idx = j + lane;
            if (idx < BPB)
                m = fminf(m, __ldcg(&g_pmin[(b * BPB + idx) * 3 + w]));
        }
#pragma unroll
        for (int o = 16; o > 0; o >>= 1)
            m = fminf(m, __shfl_xor_sync(0xFFFFFFFFu, m, o));
        if (lane == 0) s_min[w] = m;
    }
    __syncthreads();
    const float n0 = s_min[0], n1 = s_min[1], n2 = s_min[2];

    // ---- mark this batch's 512 sampled voxels (dense buffer) ----
    if (tid < MM) {
        const float4 p = *(const float4*)__builtin_assume_aligned(
            &g_spts[b * MM + tid], 16);
        float sx = __ldcg(&g_spts[b * MM + tid].x);
        float sy = __ldcg(&g_spts[b * MM + tid].y);
        float sz = __ldcg(&g_spts[b * MM + tid].z);
        (void)p;
        int v = voxel_of(sx, sy, sz, n0, n1, n2);
        atomicOr(&s_mask[v >> 5], 1u << (v & 31));
    }
    __syncthreads();

    // ---- masked accumulation (REDs fire-and-forget) ----
    if (active) {
        float px[4] = {f0.x, f0.w, f1.z, f2.y};
        float py[4] = {f0.y, f1.x, f1.w, f2.z};
        float pz[4] = {f0.z, f1.y, f2.x, f2.w};
#pragma unroll
        for (int k = 0; k < 4; k++) {
            int v = voxel_of(px[k], py[k], pz[k], n0, n1, n2);
            if (s_mask[v >> 5] & (1u << (v & 31))) {
                float* a = &g_acc[(size_t)(b * VV + v) * 10];
                atomicAdd(a + 0, 1.0f);
                atomicAdd(a + 1, px[k]);
                atomicAdd(a + 2, py[k]);
                atomicAdd(a + 3, pz[k]);
                atomicAdd(a + 4, px[k] * px[k]);
                atomicAdd(a + 5, px[k] * py[k]);
                atomicAdd(a + 6, px[k] * pz[k]);
                atomicAdd(a + 7, py[k] * py[k]);
                atomicAdd(a + 8, py[k] * pz[k]);
                atomicAdd(a + 9, pz[k] * pz[k]);
            }
        }
    }
}

// ============================================================================
// K_B (1 block x 1024): gather + finalize; then restore scratch state.
// ============================================================================
__global__ void __launch_bounds__(1024)
kB(float* __restrict__ out) {
    const int tid = threadIdx.x;                 // 0..1023 = b*MM + j
    const int b = tid >> 9;
    const int lane = tid & 31, w = tid >> 5;
    __shared__ float s_min[6];                   // [batch*3 + comp]

    // re-reduce mins for both batches: 6 warps (batch, component)
    if (w < 6) {
        int rb = w / 3, c = w % 3;
        float m = CUDART_INF_F;
#pragma unroll
        for (int j = 0; j < BPB; j += 32) {
            int idx = j + lane;
            if (idx < BPB)
                m = fminf(m, g_pmin[(rb * BPB + idx) * 3 + c]);
        }
#pragma unroll
        for (int o = 16; o > 0; o >>= 1)
            m = fminf(m, __shfl_xor_sync(0xFFFFFFFFu, m, o));
        if (lane == 0) s_min[w] = m;
    }
    __syncthreads();

    float4 p = g_spts[tid];
    int v = voxel_of(p.x, p.y, p.z, s_min[b*3+0], s_min[b*3+1], s_min[b*3+2]);
    float* a = &g_acc[(size_t)(b * VV + v) * 10];

    float c0 = a[0];
    float s1 = a[1], s2 = a[2], s3 = a[3];
    float q4 = a[4], q5 = a[5], q6 = a[6];
    float q7 = a[7], q8 = a[8], q9 = a[9];

    // all reads complete before any thread zeroes shared voxel entries
    __syncthreads();
#pragma unroll
    for (int k = 0; k < 10; k++) a[k] = 0.0f;    // keep g_acc zero for next run
    if (tid == 0) g_done = 0u;                   // re-arm barrier counter

    float inv = 1.0f / fmaxf(c0, 1.0f);
    float mx = s1 * inv, my = s2 * inv, mz = s3 * inv;
    float cxx = q4 * inv - mx * mx;
    float cxy = q5 * inv - mx * my;
    float cxz = q6 * inv - mx * mz;
    float cyy = q7 * inv - my * my;
    float cyz = q8 * inv - my * mz;
    float czz = q9 * inv - mz * mz;

    float* o = out + (size_t)tid * 12;
    o[0] = mx;  o[1] = my;  o[2] = mz;
    o[3] = cxx; o[4] = cxy; o[5] = cxz;
    o[6] = cxy; o[7] = cyy; o[8] = cyz;
    o[9] = cxz; o[10] = cyz; o[11] = czz;
}

// ---------------------------------------------------------------------------
extern "C" void kernel_launch(void* const* d_in, const int* in_sizes, int n_in,
                              void* d_out, int out_size) {
    const float* x    = (const float*)d_in[0];   // (B, N, 3) f32
    const int*   sidx = (const int*)d_in[1];     // (B, M) i32
    float*       out  = (float*)d_out;           // (B, M, 12) f32

    kA<<<NBLK, NTHR>>>(x, sidx);
    kB<<<1, 1024>>>(out);
}

// round 9
// speedup vs baseline: 1.8450x; 1.4820x over previous
#include <cuda_runtime.h>
#include <cstdint>
#include <math_constants.h>

// Problem constants: B=2, N=131072, M=512, G=20
#define BB 2
#define NN 131072
#define MM 512
#define GG 20
#define VV 8000
#define VOXINV 2.0f

#define NBLK 148                // one wave on 148+ SMs
#define BPB  74                 // blocks per batch
#define NTHR 512
#define GROUPS 32768            // NN/4 float4-groups per batch
#define MASKW 250               // VV bits / 32
#define VSTRIDE 12              // padded voxel record: 48B, 16B-aligned
#define ACCW (BB * VV * VSTRIDE / 4)   // 48000 uint4 words

// Device scratch. g_minc seeded +inf at load, re-armed by k3 every launch.
__device__ unsigned int g_minc[BB * 3] = {
    0x7F800000u, 0x7F800000u, 0x7F800000u,
    0x7F800000u, 0x7F800000u, 0x7F800000u};
__device__ float4 g_spts[BB * MM];                // compacted sampled points
__device__ __align__(16) float g_acc[BB * VV * VSTRIDE];
// layout per voxel: [cnt, sx, sy, sz][xx, xy, xz, yy][yz, zz, pad, pad]

__device__ __forceinline__ int voxel_of(float px, float py, float pz,
                                        float n0, float n1, float n2) {
    int vx = (int)floorf((px - n0) * VOXINV);
    int vy = (int)floorf((py - n1) * VOXINV);
    int vz = (int)floorf((pz - n2) * VOXINV);
    vx = min(max(vx, 0), GG - 1);
    vy = min(max(vy, 0), GG - 1);
    vz = min(max(vz, 0), GG - 1);
    return (vx * GG + vy) * GG + vz;
}

// ============================================================================
// K1: zero g_acc (single shot) + compact sampled points + global min.
// ============================================================================
__global__ void __launch_bounds__(NTHR)
k1_min(const float* __restrict__ x, const int* __restrict__ sidx) {
    const int bid = blockIdx.x, tid = threadIdx.x;
    const int b = (bid < BPB) ? 0 : 1, br = bid - b * BPB;
    const int lane = tid & 31, w = tid >> 5;
    const int t = bid * NTHR + tid;      // 0..75775
    __shared__ float s_red[16 * 3];

    // zero accumulators: 48000 uint4 over 75776 threads, single shot
    if (t < ACCW) ((uint4*)g_acc)[t] = make_uint4(0u, 0u, 0u, 0u);

    // compact sampled points (one scattered gather per launch)
    if (t < BB * MM) {
        int sb = t >> 9;
        int i = __ldg(sidx + t);
        const float* p = x + ((size_t)sb * NN + i) * 3;
        g_spts[t] = make_float4(__ldg(p), __ldg(p + 1), __ldg(p + 2), 0.0f);
    }

    // coordinate min: one float4-group (4 points) per active thread
    float m0 = CUDART_INF_F, m1 = CUDART_INF_F, m2 = CUDART_INF_F;
    {
        const float4* xb = (const float4*)(x + (size_t)b * NN * 3);
        int g = br * NTHR + tid;
        if (g < GROUPS) {
            float4 f0 = __ldg(xb + (size_t)g * 3 + 0);
            float4 f1 = __ldg(xb + (size_t)g * 3 + 1);
            float4 f2 = __ldg(xb + (size_t)g * 3 + 2);
            m0 = fminf(fminf(f0.x, f0.w), fminf(f1.z, f2.y));
            m1 = fminf(fminf(f0.y, f1.x), fminf(f1.w, f2.z));
            m2 = fminf(fminf(f0.z, f1.y), fminf(f2.x, f2.w));
        }
    }
#pragma unroll
    for (int o = 16; o > 0; o >>= 1) {
        m0 = fminf(m0, __shfl_xor_sync(0xFFFFFFFFu, m0, o));
        m1 = fminf(m1, __shfl_xor_sync(0xFFFFFFFFu, m1, o));
        m2 = fminf(m2, __shfl_xor_sync(0xFFFFFFFFu, m2, o));
    }
    if (lane == 0) { s_red[w*3+0] = m0; s_red[w*3+1] = m1; s_red[w*3+2] = m2; }
    __syncthreads();
    if (tid == 0) {
        float r0 = s_red[0], r1 = s_red[1], r2 = s_red[2];
#pragma unroll
        for (int k = 1; k < 16; k++) {
            r0 = fminf(r0, s_red[k*3+0]);
            r1 = fminf(r1, s_red[k*3+1]);
            r2 = fminf(r2, s_red[k*3+2]);
        }
        // positive floats: uint bit order == float order
        atomicMin(&g_minc[b*3+0], __float_as_uint(r0));
        atomicMin(&g_minc[b*3+1], __float_as_uint(r1));
        atomicMin(&g_minc[b*3+2], __float_as_uint(r2));
    }
}

// ============================================================================
// K2: smem mark from dense sampled buffer + masked vector-RED accumulation.
// ============================================================================
__global__ void __launch_bounds__(NTHR)
k2_accum(const float* __restrict__ x) {
    const int bid = blockIdx.x, tid = threadIdx.x;
    const int b = (bid < BPB) ? 0 : 1, br = bid - b * BPB;
    __shared__ unsigned int s_mask[MASKW];

    if (tid < MASKW) s_mask[tid] = 0u;
    const float n0 = __uint_as_float(g_minc[b*3+0]);
    const float n1 = __uint_as_float(g_minc[b*3+1]);
    const float n2 = __uint_as_float(g_minc[b*3+2]);
    __syncthreads();

    // mark this batch's 512 sampled voxels (dense buffer, 1 point/thread)
    if (tid < MM) {
        float4 p = g_spts[b * MM + tid];
        int v = voxel_of(p.x, p.y, p.z, n0, n1, n2);
        atomicOr(&s_mask[v >> 5], 1u << (v & 31));
    }
    __syncthreads();

    // masked accumulation: one float4-group (4 points) per thread
    const int g = br * NTHR + tid;
    if (g < GROUPS) {
        const float4* xb = (const float4*)(x + (size_t)b * NN * 3);
        float4 f0 = __ldg(xb + (size_t)g * 3 + 0);
        float4 f1 = __ldg(xb + (size_t)g * 3 + 1);
        float4 f2 = __ldg(xb + (size_t)g * 3 + 2);
        float px[4] = {f0.x, f0.w, f1.z, f2.y};
        float py[4] = {f0.y, f1.x, f1.w, f2.z};
        float pz[4] = {f0.z, f1.y, f2.x, f2.w};
#pragma unroll
        for (int k = 0; k < 4; k++) {
            int v = voxel_of(px[k], py[k], pz[k], n0, n1, n2);
            if (s_mask[v >> 5] & (1u << (v & 31))) {
                float* a = &g_acc[(size_t)(b * VV + v) * VSTRIDE];
                // 3 vector REDs instead of 10 scalar ones (sm_90+)
                asm volatile(
                    "red.add.v4.f32 [%0], {%1, %2, %3, %4};"
                    :: "l"(a), "f"(1.0f), "f"(px[k]), "f"(py[k]), "f"(pz[k])
                    : "memory");
                asm volatile(
                    "red.add.v4.f32 [%0], {%1, %2, %3, %4};"
                    :: "l"(a + 4), "f"(px[k] * px[k]), "f"(px[k] * py[k]),
                       "f"(px[k] * pz[k]), "f"(py[k] * py[k])
                    : "memory");
                asm volatile(
                    "red.add.v2.f32 [%0], {%1, %2};"
                    :: "l"(a + 8), "f"(py[k] * pz[k]), "f"(pz[k] * pz[k])
                    : "memory");
            }
        }
    }
}

// ============================================================================
// K3: gather + finalize output (B, M, 12); re-arm g_minc for next launch.
// grid = 4 x 256 (threads map 1:1 to the 1024 outputs)
// ============================================================================
__global__ void __launch_bounds__(256)
k3_out(float* __restrict__ out) {
    const int t = blockIdx.x * 256 + threadIdx.x;   // 0..1023
    const int b = t >> 9;
    const float n0 = __uint_as_float(g_minc[b*3+0]);
    const float n1 = __uint_as_float(g_minc[b*3+1]);
    const float n2 = __uint_as_float(g_minc[b*3+2]);

    float4 p = g_spts[t];
    int v = voxel_of(p.x, p.y, p.z, n0, n1, n2);
    const float* a = &g_acc[(size_t)(b * VV + v) * VSTRIDE];

    float inv = 1.0f / fmaxf(a[0], 1.0f);
    float mx = a[1] * inv, my = a[2] * inv, mz = a[3] * inv;
    float cxx = a[4] * inv - mx * mx;
    float cxy = a[5] * inv - mx * my;
    float cxz = a[6] * inv - mx * mz;
    float cyy = a[7] * inv - my * my;
    float cyz = a[8] * inv - my * mz;
    float czz = a[9] * inv - mz * mz;

    float* o = out + (size_t)t * 12;
    o[0] = mx;  o[1] = my;  o[2] = mz;
    o[3] = cxx; o[4] = cxy; o[5] = cxz;
    o[6] = cxy; o[7] = cyy; o[8] = cyz;
    o[9] = cxz; o[10] = cyz; o[11] = czz;

    // re-arm min for the next replay (graph nodes serialize)
    if (t < BB * 3) g_minc[t] = 0x7F800000u;
}

// ---------------------------------------------------------------------------
extern "C" void kernel_launch(void* const* d_in, const int* in_sizes, int n_in,
                              void* d_out, int out_size) {
    const float* x    = (const float*)d_in[0];   // (B, N, 3) f32
    const int*   sidx = (const int*)d_in[1];     // (B, M) i32
    float*       out  = (float*)d_out;           // (B, M, 12) f32

    k1_min<<<NBLK, NTHR>>>(x, sidx);
    k2_accum<<<NBLK, NTHR>>>(x);
    k3_out<<<4, 256>>>(out);
}

// round 10
// speedup vs baseline: 2.1737x; 1.1782x over previous
#include <cuda_runtime.h>
#include <cstdint>
#include <math_constants.h>

// Problem constants: B=2, N=131072, M=512, G=20
#define BB 2
#define NN 131072
#define MM 512
#define GG 20
#define VV 8000
#define VOXINV 2.0f

#define NBLK 148                // one wave; all blocks co-resident (<= 148 SMs)
#define BPB  74                 // blocks per batch
#define NTHR 512                // == MM: mark phase is exactly 1 point/thread
#define GROUPS 32768            // NN/4 float4-groups per batch
#define MASKW 250               // VV bits / 32
#define ACCW 40000              // BB*VV*10 floats / 4 = uint4 words

// Device scratch. g_done zero at load, reset by kB each launch.
__device__ float        g_pmin[NBLK * 3];     // per-block partial mins
__device__ float4       g_spts[BB * MM];      // compacted sampled points
__device__ float        g_acc[BB * VV * 10];  // cnt, sx..sz, xx,xy,xz,yy,yz,zz
__device__ unsigned int g_done;               // grid-barrier arrival counter

__device__ __forceinline__ int voxel_of(float px, float py, float pz,
                                        float n0, float n1, float n2) {
    int vx = (int)floorf((px - n0) * VOXINV);
    int vy = (int)floorf((py - n1) * VOXINV);
    int vz = (int)floorf((pz - n2) * VOXINV);
    vx = min(max(vx, 0), GG - 1);
    vy = min(max(vy, 0), GG - 1);
    vz = min(max(vz, 0), GG - 1);
    return (vx * GG + vy) * GG + vz;
}

// ============================================================================
// K_A: zero + compact + partial min -> pre-RED grid barrier -> mark + accum.
// ============================================================================
__global__ void __launch_bounds__(NTHR)
kA(const float* __restrict__ x, const int* __restrict__ sidx) {
    const int bid = blockIdx.x, tid = threadIdx.x;
    const int b = (bid < BPB) ? 0 : 1, br = bid - b * BPB;
    const int lane = tid & 31, w = tid >> 5;
    const int t = bid * NTHR + tid;      // 0..75775
    __shared__ float s_red[16 * 3];
    __shared__ float s_min[3];
    __shared__ unsigned int s_mask[MASKW];

    if (tid < MASKW) s_mask[tid] = 0u;

    // zero accumulators: 40000 uint4 over 75776 threads, single shot
    if (t < ACCW) ((uint4*)g_acc)[t] = make_uint4(0u, 0u, 0u, 0u);

    // compact sampled points (one scattered gather)
    if (t < BB * MM) {
        int sb = t >> 9;
        int i = __ldg(sidx + t);
        const float* p = x + ((size_t)sb * NN + i) * 3;
        g_spts[t] = make_float4(__ldg(p), __ldg(p + 1), __ldg(p + 2), 0.0f);
    }

    // this thread's 4 points: reused for min now and accumulation later
    const int g = br * NTHR + tid;
    const bool active = (g < GROUPS);
    float4 f0, f1, f2;
    float m0 = CUDART_INF_F, m1 = CUDART_INF_F, m2 = CUDART_INF_F;
    if (active) {
        const float4* xb = (const float4*)(x + (size_t)b * NN * 3);
        f0 = __ldg(xb + (size_t)g * 3 + 0);
        f1 = __ldg(xb + (size_t)g * 3 + 1);
        f2 = __ldg(xb + (size_t)g * 3 + 2);
        m0 = fminf(fminf(f0.x, f0.w), fminf(f1.z, f2.y));
        m1 = fminf(fminf(f0.y, f1.x), fminf(f1.w, f2.z));
        m2 = fminf(fminf(f0.z, f1.y), fminf(f2.x, f2.w));
    }
#pragma unroll
    for (int o = 16; o > 0; o >>= 1) {
        m0 = fminf(m0, __shfl_xor_sync(0xFFFFFFFFu, m0, o));
        m1 = fminf(m1, __shfl_xor_sync(0xFFFFFFFFu, m1, o));
        m2 = fminf(m2, __shfl_xor_sync(0xFFFFFFFFu, m2, o));
    }
    if (lane == 0) { s_red[w*3+0] = m0; s_red[w*3+1] = m1; s_red[w*3+2] = m2; }
    __syncthreads();
    if (tid == 0) {
        float r0 = s_red[0], r1 = s_red[1], r2 = s_red[2];
#pragma unroll
        for (int k = 1; k < 16; k++) {
            r0 = fminf(r0, s_red[k*3+0]);
            r1 = fminf(r1, s_red[k*3+1]);
            r2 = fminf(r2, s_red[k*3+2]);
        }
        g_pmin[bid*3+0] = r0; g_pmin[bid*3+1] = r1; g_pmin[bid*3+2] = r2;
    }

    // ---- grid barrier: fence drains only plain stores (no REDs yet) ----
    __syncthreads();
    if (tid == 0) {
        __threadfence();                            // publish g_pmin/g_spts/g_acc
        atomicAdd(&g_done, 1u);
        while (atomicAdd(&g_done, 0u) < NBLK) { __nanosleep(64); }
    }
    __syncthreads();

    // re-reduce this batch's min (3 warps, one component each; L2-scope loads)
    if (w < 3) {
        float m = CUDART_INF_F;
#pragma unroll
        for (int j = 0; j < BPB; j += 32) {
            int idx = j + lane;
            if (idx < BPB)
                m = fminf(m, __ldcg(&g_pmin[(b * BPB + idx) * 3 + w]));
        }
#pragma unroll
        for (int o = 16; o > 0; o >>= 1)
            m = fminf(m, __shfl_xor_sync(0xFFFFFFFFu, m, o));
        if (lane == 0) s_min[w] = m;
    }
    __syncthreads();
    const float n0 = s_min[0], n1 = s_min[1], n2 = s_min[2];

    // mark this batch's 512 sampled voxels: exactly one point per thread
    {
        const float4* sp = &g_spts[b * MM + tid];
        float sx = __ldcg(&sp->x), sy = __ldcg(&sp->y), sz = __ldcg(&sp->z);
        int v = voxel_of(sx, sy, sz, n0, n1, n2);
        atomicOr(&s_mask[v >> 5], 1u << (v & 31));
    }
    __syncthreads();

    // masked accumulation: scalar REDs, fire-and-forget
    if (active) {
        float px[4] = {f0.x, f0.w, f1.z, f2.y};
        float py[4] = {f0.y, f1.x, f1.w, f2.z};
        float pz[4] = {f0.z, f1.y, f2.x, f2.w};
#pragma unroll
        for (int k = 0; k < 4; k++) {
            int v = voxel_of(px[k], py[k], pz[k], n0, n1, n2);
            if (s_mask[v >> 5] & (1u << (v & 31))) {
                float* a = &g_acc[(size_t)(b * VV + v) * 10];
                atomicAdd(a + 0, 1.0f);
                atomicAdd(a + 1, px[k]);
                atomicAdd(a + 2, py[k]);
                atomicAdd(a + 3, pz[k]);
                atomicAdd(a + 4, px[k] * px[k]);
                atomicAdd(a + 5, px[k] * py[k]);
                atomicAdd(a + 6, px[k] * pz[k]);
                atomicAdd(a + 7, py[k] * py[k]);
                atomicAdd(a + 8, py[k] * pz[k]);
                atomicAdd(a + 9, pz[k] * pz[k]);
            }
        }
    }
}

// ============================================================================
// K_B (4 blocks x 256, multi-block => no single-SM LSU bottleneck):
// gather + finalize output; reset barrier counter for next replay.
// ============================================================================
__global__ void __launch_bounds__(256)
kB(float* __restrict__ out) {
    const int bid = blockIdx.x, tid = threadIdx.x;
    const int t = bid * 256 + tid;               // 0..1023 = b*MM + j
    const int b = t >> 9;
    const int lane = tid & 31, w = tid >> 5;
    __shared__ float s_min[3];

    if (t == 0) g_done = 0u;                     // re-arm grid barrier

    // re-reduce this batch's min (3 warps)
    if (w < 3) {
        float m = CUDART_INF_F;
#pragma unroll
        for (int j = 0; j < BPB; j += 32) {
            int idx = j + lane;
            if (idx < BPB)
                m = fminf(m, g_pmin[(b * BPB + idx) * 3 + w]);
        }
#pragma unroll
        for (int o = 16; o > 0; o >>= 1)
            m = fminf(m, __shfl_xor_sync(0xFFFFFFFFu, m, o));
        if (lane == 0) s_min[w] = m;
    }
    __syncthreads();

    float4 p = g_spts[t];
    int v = voxel_of(p.x, p.y, p.z, s_min[0], s_min[1], s_min[2]);
    const float* a = &g_acc[(size_t)(b * VV + v) * 10];

    float inv = 1.0f / fmaxf(a[0], 1.0f);
    float mx = a[1] * inv, my = a[2] * inv, mz = a[3] * inv;
    float cxx = a[4] * inv - mx * mx;
    float cxy = a[5] * inv - mx * my;
    float cxz = a[6] * inv - mx * mz;
    float cyy = a[7] * inv - my * my;
    float cyz = a[8] * inv - my * mz;
    float czz = a[9] * inv - mz * mz;

    float* o = out + (size_t)t * 12;
    o[0] = mx;  o[1] = my;  o[2] = mz;
    o[3] = cxx; o[4] = cxy; o[5] = cxz;
    o[6] = cxy; o[7] = cyy; o[8] = cyz;
    o[9] = cxz; o[10] = cyz; o[11] = czz;
}

// ---------------------------------------------------------------------------
extern "C" void kernel_launch(void* const* d_in, const int* in_sizes, int n_in,
                              void* d_out, int out_size) {
    const float* x    = (const float*)d_in[0];   // (B, N, 3) f32
    const int*   sidx = (const int*)d_in[1];     // (B, M) i32
    float*       out  = (float*)d_out;           // (B, M, 12) f32

    kA<<<NBLK, NTHR>>>(x, sidx);
    kB<<<4, 256>>>(out);
}

// round 11
// speedup vs baseline: 2.3922x; 1.1005x over previous
#include <cuda_runtime.h>
#include <cstdint>
#include <math_constants.h>

// Problem constants: B=2, N=131072, M=512, G=20
#define BB 2
#define NN 131072
#define MM 512
#define GG 20
#define VV 8000
#define VOXINV 2.0f

#define NBLK 148                // one wave on 148+ SMs
#define BPB  74                 // blocks per batch
#define NTHR 512                // single-shot: one float4-group per thread
#define GROUPS 32768            // NN/4 float4-groups per batch
#define MASKW 250               // VV bits / 32
#define ACCW 40000              // BB*VV*10 floats / 4 = uint4 words

// Device scratch. g_minc seeded +inf at load, re-armed by k3 every launch
// (graph nodes serialize -> deterministic per launch).
__device__ unsigned int g_minc[BB * 3] = {
    0x7F800000u, 0x7F800000u, 0x7F800000u,
    0x7F800000u, 0x7F800000u, 0x7F800000u};
__device__ float4 g_spts[BB * MM];      // compacted sampled points (.w unused)
__device__ __align__(16) float g_acc[BB * VV * 10];  // cnt,sx..sz,xx..zz

__device__ __forceinline__ int voxel_of(float px, float py, float pz,
                                        float n0, float n1, float n2) {
    int vx = (int)floorf((px - n0) * VOXINV);
    int vy = (int)floorf((py - n1) * VOXINV);
    int vz = (int)floorf((pz - n2) * VOXINV);
    vx = min(max(vx, 0), GG - 1);
    vy = min(max(vy, 0), GG - 1);
    vz = min(max(vz, 0), GG - 1);
    return (vx * GG + vy) * GG + vz;
}

// ============================================================================
// K1: zero g_acc (single shot) + compact sampled points + global min.
// ============================================================================
__global__ void __launch_bounds__(NTHR)
k1_min(const float* __restrict__ x, const int* __restrict__ sidx) {
    const int bid = blockIdx.x, tid = threadIdx.x;
    const int b = (bid < BPB) ? 0 : 1, br = bid - b * BPB;
    const int lane = tid & 31, w = tid >> 5;
    const int t = bid * NTHR + tid;      // 0..75775
    __shared__ float s_red[16 * 3];

    // zero accumulators: 40000 uint4 over 75776 threads, single shot
    if (t < ACCW) ((uint4*)g_acc)[t] = make_uint4(0u, 0u, 0u, 0u);

    // compact sampled points (the only scattered gather in the pipeline)
    if (t < BB * MM) {
        int sb = t >> 9;
        int i = __ldg(sidx + t);
        const float* p = x + ((size_t)sb * NN + i) * 3;
        g_spts[t] = make_float4(__ldg(p), __ldg(p + 1), __ldg(p + 2), 0.0f);
    }

    // coordinate min: one float4-group (4 points) per active thread
    float m0 = CUDART_INF_F, m1 = CUDART_INF_F, m2 = CUDART_INF_F;
    {
        const float4* xb = (const float4*)(x + (size_t)b * NN * 3);
        int g = br * NTHR + tid;
        if (g < GROUPS) {
            float4 f0 = __ldg(xb + (size_t)g * 3 + 0);
            float4 f1 = __ldg(xb + (size_t)g * 3 + 1);
            float4 f2 = __ldg(xb + (size_t)g * 3 + 2);
            m0 = fminf(fminf(f0.x, f0.w), fminf(f1.z, f2.y));
            m1 = fminf(fminf(f0.y, f1.x), fminf(f1.w, f2.z));
            m2 = fminf(fminf(f0.z, f1.y), fminf(f2.x, f2.w));
        }
    }
#pragma unroll
    for (int o = 16; o > 0; o >>= 1) {
        m0 = fminf(m0, __shfl_xor_sync(0xFFFFFFFFu, m0, o));
        m1 = fminf(m1, __shfl_xor_sync(0xFFFFFFFFu, m1, o));
        m2 = fminf(m2, __shfl_xor_sync(0xFFFFFFFFu, m2, o));
    }
    if (lane == 0) { s_red[w*3+0] = m0; s_red[w*3+1] = m1; s_red[w*3+2] = m2; }
    __syncthreads();
    if (tid == 0) {
        float r0 = s_red[0], r1 = s_red[1], r2 = s_red[2];
#pragma unroll
        for (int k = 1; k < 16; k++) {
            r0 = fminf(r0, s_red[k*3+0]);
            r1 = fminf(r1, s_red[k*3+1]);
            r2 = fminf(r2, s_red[k*3+2]);
        }
        // positive floats: uint bit order == float order
        atomicMin(&g_minc[b*3+0], __float_as_uint(r0));
        atomicMin(&g_minc[b*3+1], __float_as_uint(r1));
        atomicMin(&g_minc[b*3+2], __float_as_uint(r2));
    }
}

// ============================================================================
// K2: smem mark (1 sampled point/thread) + masked scalar-RED accumulation
// (exactly one float4-group per thread).
// ============================================================================
__global__ void __launch_bounds__(NTHR)
k2_accum(const float* __restrict__ x) {
    const int bid = blockIdx.x, tid = threadIdx.x;
    const int b = (bid < BPB) ? 0 : 1, br = bid - b * BPB;
    __shared__ unsigned int s_mask[MASKW];

    if (tid < MASKW) s_mask[tid] = 0u;
    const float n0 = __uint_as_float(g_minc[b*3+0]);
    const float n1 = __uint_as_float(g_minc[b*3+1]);
    const float n2 = __uint_as_float(g_minc[b*3+2]);
    __syncthreads();

    // mark this batch's 512 sampled voxels: exactly one point per thread
    {
        float4 p = g_spts[b * MM + tid];   // NTHR == MM
        int v = voxel_of(p.x, p.y, p.z, n0, n1, n2);
        atomicOr(&s_mask[v >> 5], 1u << (v & 31));
    }
    __syncthreads();

    // masked accumulation: one float4-group (4 points) per thread
    const int g = br * NTHR + tid;
    if (g < GROUPS) {
        const float4* xb = (const float4*)(x + (size_t)b * NN * 3);
        float4 f0 = __ldg(xb + (size_t)g * 3 + 0);
        float4 f1 = __ldg(xb + (size_t)g * 3 + 1);
        float4 f2 = __ldg(xb + (size_t)g * 3 + 2);
        float px[4] = {f0.x, f0.w, f1.z, f2.y};
        float py[4] = {f0.y, f1.x, f1.w, f2.z};
        float pz[4] = {f0.z, f1.y, f2.x, f2.w};
#pragma unroll
        for (int k = 0; k < 4; k++) {
            int v = voxel_of(px[k], py[k], pz[k], n0, n1, n2);
            if (s_mask[v >> 5] & (1u << (v & 31))) {
                float* a = &g_acc[(size_t)(b * VV + v) * 10];
                atomicAdd(a + 0, 1.0f);
                atomicAdd(a + 1, px[k]);
                atomicAdd(a + 2, py[k]);
                atomicAdd(a + 3, pz[k]);
                atomicAdd(a + 4, px[k] * px[k]);
                atomicAdd(a + 5, px[k] * py[k]);
                atomicAdd(a + 6, px[k] * pz[k]);
                atomicAdd(a + 7, py[k] * py[k]);
                atomicAdd(a + 8, py[k] * pz[k]);
                atomicAdd(a + 9, pz[k] * pz[k]);
            }
        }
    }
}

// ============================================================================
// K3: gather + finalize output (B, M, 12); re-arm g_minc for next launch.
// grid = 4 x 256; float2 record loads (records are 8B-aligned, 40B).
// ============================================================================
__global__ void __launch_bounds__(256)
k3_out(float* __restrict__ out) {
    const int t = blockIdx.x * 256 + threadIdx.x;   // 0..1023
    const int b = t >> 9;
    const float n0 = __uint_as_float(g_minc[b*3+0]);
    const float n1 = __uint_as_float(g_minc[b*3+1]);
    const float n2 = __uint_as_float(g_minc[b*3+2]);

    float4 p = g_spts[t];
    int v = voxel_of(p.x, p.y, p.z, n0, n1, n2);
    const float2* a2 = (const float2*)&g_acc[(size_t)(b * VV + v) * 10];

    float2 r0 = a2[0];   // cnt, sx
    float2 r1 = a2[1];   // sy, sz
    float2 r2 = a2[2];   // xx, xy
    float2 r3 = a2[3];   // xz, yy
    float2 r4 = a2[4];   // yz, zz

    float inv = 1.0f / fmaxf(r0.x, 1.0f);
    float mx = r0.y * inv, my = r1.x * inv, mz = r1.y * inv;
    float cxx = r2.x * inv - mx * mx;
    float cxy = r2.y * inv - mx * my;
    float cxz = r3.x * inv - mx * mz;
    float cyy = r3.y * inv - my * my;
    float cyz = r4.x * inv - my * mz;
    float czz = r4.y * inv - mz * mz;

    float* o = out + (size_t)t * 12;
    o[0] = mx;  o[1] = my;  o[2] = mz;
    o[3] = cxx; o[4] = cxy; o[5] = cxz;
    o[6] = cxy; o[7] = cyy; o[8] = cyz;
    o[9] = cxz; o[10] = cyz; o[11] = czz;

    // re-arm min for the next replay (graph nodes serialize)
    if (t < BB * 3) g_minc[t] = 0x7F800000u;
}

// ---------------------------------------------------------------------------
extern "C" void kernel_launch(void* const* d_in, const int* in_sizes, int n_in,
                              void* d_out, int out_size) {
    const float* x    = (const float*)d_in[0];   // (B, N, 3) f32
    const int*   sidx = (const int*)d_in[1];     // (B, M) i32
    float*       out  = (float*)d_out;           // (B, M, 12) f32

    k1_min<<<NBLK, NTHR>>>(x, sidx);
    k2_accum<<<NBLK, NTHR>>>(x);
    k3_out<<<4, 256>>>(out);
}

// round 12
// speedup vs baseline: 2.4039x; 1.0049x over previous
#include <cuda_runtime.h>
#include <cstdint>
#include <math_constants.h>

// Problem constants: B=2, N=131072, M=512, G=20
#define BB 2
#define NN 131072
#define MM 512
#define GG 20
#define VV 8000
#define VOXINV 2.0f

#define NTHR 256
#define BPB  148                // blocks per batch
#define NBLK (BB * BPB)         // 296 = 2 CTAs/SM, one co-resident wave
#define GROUPS 32768            // NN/4 float4-groups per batch
#define MASKW 250               // VV bits / 32
#define ACCW 40000              // BB*VV*10 floats / 4 = uint4 words

// Device scratch. g_minc seeded +inf at load, re-armed by k3 every launch
// (graph nodes serialize -> deterministic per launch).
__device__ unsigned int g_minc[BB * 3] = {
    0x7F800000u, 0x7F800000u, 0x7F800000u,
    0x7F800000u, 0x7F800000u, 0x7F800000u};
__device__ float4 g_spts[BB * MM];      // compacted sampled points (.w unused)
__device__ __align__(16) float g_acc[BB * VV * 10];  // cnt,sx..sz,xx..zz

__device__ __forceinline__ int voxel_of(float px, float py, float pz,
                                        float n0, float n1, float n2) {
    int vx = (int)floorf((px - n0) * VOXINV);
    int vy = (int)floorf((py - n1) * VOXINV);
    int vz = (int)floorf((pz - n2) * VOXINV);
    vx = min(max(vx, 0), GG - 1);
    vy = min(max(vy, 0), GG - 1);
    vz = min(max(vz, 0), GG - 1);
    return (vx * GG + vy) * GG + vz;
}

// ============================================================================
// K1: zero g_acc (single shot) + compact sampled points + global min.
// ============================================================================
__global__ void __launch_bounds__(NTHR)
k1_min(const float* __restrict__ x, const int* __restrict__ sidx) {
    const int bid = blockIdx.x, tid = threadIdx.x;
    const int b = (bid < BPB) ? 0 : 1, br = bid - b * BPB;
    const int lane = tid & 31, w = tid >> 5;
    const int t = bid * NTHR + tid;      // 0..75775
    __shared__ float s_red[8 * 3];

    // zero accumulators: 40000 uint4 over 75776 threads, single shot
    if (t < ACCW) ((uint4*)g_acc)[t] = make_uint4(0u, 0u, 0u, 0u);

    // compact sampled points (the only scattered gather in the pipeline)
    if (t < BB * MM) {
        int sb = t >> 9;
        int i = __ldg(sidx + t);
        const float* p = x + ((size_t)sb * NN + i) * 3;
        g_spts[t] = make_float4(__ldg(p), __ldg(p + 1), __ldg(p + 2), 0.0f);
    }

    // coordinate min: one float4-group (4 points) per active thread
    float m0 = CUDART_INF_F, m1 = CUDART_INF_F, m2 = CUDART_INF_F;
    {
        const float4* xb = (const float4*)(x + (size_t)b * NN * 3);
        int g = br * NTHR + tid;
        if (g < GROUPS) {
            float4 f0 = __ldg(xb + (size_t)g * 3 + 0);
            float4 f1 = __ldg(xb + (size_t)g * 3 + 1);
            float4 f2 = __ldg(xb + (size_t)g * 3 + 2);
            m0 = fminf(fminf(f0.x, f0.w), fminf(f1.z, f2.y));
            m1 = fminf(fminf(f0.y, f1.x), fminf(f1.w, f2.z));
            m2 = fminf(fminf(f0.z, f1.y), fminf(f2.x, f2.w));
        }
    }
#pragma unroll
    for (int o = 16; o > 0; o >>= 1) {
        m0 = fminf(m0, __shfl_xor_sync(0xFFFFFFFFu, m0, o));
        m1 = fminf(m1, __shfl_xor_sync(0xFFFFFFFFu, m1, o));
        m2 = fminf(m2, __shfl_xor_sync(0xFFFFFFFFu, m2, o));
    }
    if (lane == 0) { s_red[w*3+0] = m0; s_red[w*3+1] = m1; s_red[w*3+2] = m2; }
    __syncthreads();
    if (tid == 0) {
        float r0 = s_red[0], r1 = s_red[1], r2 = s_red[2];
#pragma unroll
        for (int k = 1; k < 8; k++) {
            r0 = fminf(r0, s_red[k*3+0]);
            r1 = fminf(r1, s_red[k*3+1]);
            r2 = fminf(r2, s_red[k*3+2]);
        }
        // positive floats: uint bit order == float order
        atomicMin(&g_minc[b*3+0], __float_as_uint(r0));
        atomicMin(&g_minc[b*3+1], __float_as_uint(r1));
        atomicMin(&g_minc[b*3+2], __float_as_uint(r2));
    }
}

// ============================================================================
// K2: early x loads -> smem mark (2 sampled points/thread) -> masked
// scalar-RED accumulation (exactly one float4-group per thread).
// ============================================================================
__global__ void __launch_bounds__(NTHR)
k2_accum(const float* __restrict__ x) {
    const int bid = blockIdx.x, tid = threadIdx.x;
    const int b = (bid < BPB) ? 0 : 1, br = bid - b * BPB;
    __shared__ unsigned int s_mask[MASKW];

    if (tid < MASKW) s_mask[tid] = 0u;

    // issue this thread's point-group loads EARLY (independent of mark work)
    const int g = br * NTHR + tid;
    const bool active = (g < GROUPS);
    float4 f0, f1, f2;
    if (active) {
        const float4* xb = (const float4*)(x + (size_t)b * NN * 3);
        f0 = __ldg(xb + (size_t)g * 3 + 0);
        f1 = __ldg(xb + (size_t)g * 3 + 1);
        f2 = __ldg(xb + (size_t)g * 3 + 2);
    }

    const float n0 = __uint_as_float(g_minc[b*3+0]);
    const float n1 = __uint_as_float(g_minc[b*3+1]);
    const float n2 = __uint_as_float(g_minc[b*3+2]);
    __syncthreads();

    // mark this batch's 512 sampled voxels: two points per thread
    {
        float4 p0 = g_spts[b * MM + tid];
        float4 p1 = g_spts[b * MM + tid + NTHR];
        int v0 = voxel_of(p0.x, p0.y, p0.z, n0, n1, n2);
        int v1 = voxel_of(p1.x, p1.y, p1.z, n0, n1, n2);
        atomicOr(&s_mask[v0 >> 5], 1u << (v0 & 31));
        atomicOr(&s_mask[v1 >> 5], 1u << (v1 & 31));
    }
    __syncthreads();

    // masked accumulation: one float4-group (4 points) per thread
    if (active) {
        float px[4] = {f0.x, f0.w, f1.z, f2.y};
        float py[4] = {f0.y, f1.x, f1.w, f2.z};
        float pz[4] = {f0.z, f1.y, f2.x, f2.w};
#pragma unroll
        for (int k = 0; k < 4; k++) {
            int v = voxel_of(px[k], py[k], pz[k], n0, n1, n2);
            if (s_mask[v >> 5] & (1u << (v & 31))) {
                float* a = &g_acc[(size_t)(b * VV + v) * 10];
                atomicAdd(a + 0, 1.0f);
                atomicAdd(a + 1, px[k]);
                atomicAdd(a + 2, py[k]);
                atomicAdd(a + 3, pz[k]);
                atomicAdd(a + 4, px[k] * px[k]);
                atomicAdd(a + 5, px[k] * py[k]);
                atomicAdd(a + 6, px[k] * pz[k]);
                atomicAdd(a + 7, py[k] * py[k]);
                atomicAdd(a + 8, py[k] * pz[k]);
                atomicAdd(a + 9, pz[k] * pz[k]);
            }
        }
    }
}

// ============================================================================
// K3: gather + finalize output (B, M, 12); re-arm g_minc for next launch.
// grid = 4 x 256; float2 record loads (records are 40B, 8B-aligned).
// ============================================================================
__global__ void __launch_bounds__(256)
k3_out(float* __restrict__ out) {
    const int t = blockIdx.x * 256 + threadIdx.x;   // 0..1023
    const int b = t >> 9;
    const float n0 = __uint_as_float(g_minc[b*3+0]);
    const float n1 = __uint_as_float(g_minc[b*3+1]);
    const float n2 = __uint_as_float(g_minc[b*3+2]);

    float4 p = g_spts[t];
    int v = voxel_of(p.x, p.y, p.z, n0, n1, n2);
    const float2* a2 = (const float2*)&g_acc[(size_t)(b * VV + v) * 10];

    float2 r0 = a2[0];   // cnt, sx
    float2 r1 = a2[1];   // sy, sz
    float2 r2 = a2[2];   // xx, xy
    float2 r3 = a2[3];   // xz, yy
    float2 r4 = a2[4];   // yz, zz

    float inv = 1.0f / fmaxf(r0.x, 1.0f);
    float mx = r0.y * inv, my = r1.x * inv, mz = r1.y * inv;
    float cxx = r2.x * inv - mx * mx;
    float cxy = r2.y * inv - mx * my;
    float cxz = r3.x * inv - mx * mz;
    float cyy = r3.y * inv - my * my;
    float cyz = r4.x * inv - my * mz;
    float czz = r4.y * inv - mz * mz;

    float* o = out + (size_t)t * 12;
    o[0] = mx;  o[1] = my;  o[2] = mz;
    o[3] = cxx; o[4] = cxy; o[5] = cxz;
    o[6] = cxy; o[7] = cyy; o[8] = cyz;
    o[9] = cxz; o[10] = cyz; o[11] = czz;

    // re-arm min for the next replay (graph nodes serialize)
    if (t < BB * 3) g_minc[t] = 0x7F800000u;
}

// ---------------------------------------------------------------------------
extern "C" void kernel_launch(void* const* d_in, const int* in_sizes, int n_in,
                              void* d_out, int out_size) {
    const float* x    = (const float*)d_in[0];   // (B, N, 3) f32
    const int*   sidx = (const int*)d_in[1];     // (B, M) i32
    float*       out  = (float*)d_out;           // (B, M, 12) f32

    k1_min<<<NBLK, NTHR>>>(x, sidx);
    k2_accum<<<NBLK, NTHR>>>(x);
    k3_out<<<4, 256>>>(out);
}